// round 5
// baseline (speedup 1.0000x reference)
#include <cuda_runtime.h>

#define HH 4096
#define WW 4096
#define NPIX (HH * WW)

// One thread computes TWO vertically adjacent quads: rows (h0, h0+1), cols w0..w0+3.
// Rows h0-1 .. h0+2 are loaded once and shared between the two outputs.

__device__ __forceinline__ void nms_row4(
    const float up[6], const float ct[6], const float dn[6],
    const float4& t4, float o[4])
{
    const float th[4] = { t4.x, t4.y, t4.z, t4.w };
    const float RCP45 = 1.0f / 45.0f;   // RN(1/45)
    #pragma unroll
    for (int i = 0; i < 4; i++) {
        // deg = theta * f32(180/pi); single +180 if negative (matches reference)
        float deg = __fmul_rn(th[i], 57.29577951308232f);
        if (deg < 0.f) deg = __fadd_rn(deg, 180.f);
        // correctly-rounded deg/45 (Markstein mul+2fma, bit-exact vs RN divide)
        float q0 = __fmul_rn(deg, RCP45);
        float rr = __fmaf_rn(-45.f, q0, deg);
        float qf = __fmaf_rn(rr, RCP45, q0);
        int   k  = __float2int_rn(qf);      // F2I.RNI = round-half-even = jnp.round

        float a, b;
        if (k == 0 || k == 4) { a = ct[i + 2]; b = ct[i];     }   // 0 / 180 deg
        else if (k == 1)      { a = dn[i + 2]; b = up[i];     }   // 45
        else if (k == 2)      { a = dn[i + 1]; b = up[i + 1]; }   // 90
        else                  { a = dn[i];     b = up[i + 2]; }   // 135

        float cc = ct[i + 1];
        o[i] = (cc >= fmaxf(a, b)) ? cc : 0.f;
    }
}

__global__ void __launch_bounds__(256, 6) nms_kernel(
    const float* __restrict__ img,
    const float* __restrict__ theta,
    float* __restrict__ out)
{
    unsigned idx = blockIdx.x * 256u + threadIdx.x;   // 0 .. 2048*1024-1
    unsigned hp  = idx >> 10;            // row pair index
    unsigned w0  = (idx & 1023u) << 2;   // quad start column
    unsigned h0  = hp << 1;
    unsigned h1  = h0 | 1u;
    unsigned bc  = (h0 << 12) + w0;      // row h0
    unsigned bd  = bc + WW;              // row h1
    // neighbor rows, clamped (clamped rows feed only border-zeroed outputs)
    unsigned bm  = (h0 == 0)      ? bc : bc - WW;   // row h0-1
    unsigned be  = (h1 == HH - 1) ? bd : bd + WW;   // row h1+1

    // ---- 14 independent loads, front-batched ----
    const float4 t0 = __ldg(reinterpret_cast<const float4*>(theta + bc));
    const float4 t1 = __ldg(reinterpret_cast<const float4*>(theta + bd));
    const float4 vm = __ldg(reinterpret_cast<const float4*>(img + bm));
    const float4 vc = __ldg(reinterpret_cast<const float4*>(img + bc));
    const float4 vd = __ldg(reinterpret_cast<const float4*>(img + bd));
    const float4 ve = __ldg(reinterpret_cast<const float4*>(img + be));

    // halo scalars; clamp every index into [0, NPIX-1] (clamped values only
    // ever feed border-zeroed pixels)
    int lmi = (int)bm - 1; if (lmi < 0) lmi = 0;
    int lci = (int)bc - 1; if (lci < 0) lci = 0;
    int rei = (int)be + 4; if (rei > NPIX - 1) rei = NPIX - 1;
    int rdi = (int)bd + 4; if (rdi > NPIX - 1) rdi = NPIX - 1;

    const float lm = __ldg(img + lmi);
    const float rm = __ldg(img + bm + 4);
    const float lc = __ldg(img + lci);
    const float rc = __ldg(img + bc + 4);
    const float ld_ = __ldg(img + bd - 1);
    const float rd_ = __ldg(img + rdi);
    const float le = __ldg(img + be - 1);
    const float re = __ldg(img + rei);

    // column j = image column (w0 - 1 + j)
    const float rowm[6] = { lm,  vm.x, vm.y, vm.z, vm.w, rm  };
    const float rowc[6] = { lc,  vc.x, vc.y, vc.z, vc.w, rc  };
    const float rowd[6] = { ld_, vd.x, vd.y, vd.z, vd.w, rd_ };
    const float rowe[6] = { le,  ve.x, ve.y, ve.z, ve.w, re  };

    float o0[4], o1[4];
    nms_row4(rowm, rowc, rowd, t0, o0);   // output row h0
    nms_row4(rowc, rowd, rowe, t1, o1);   // output row h1

    // borders
    if (h0 == 0)      { o0[0] = o0[1] = o0[2] = o0[3] = 0.f; }
    if (h1 == HH - 1) { o1[0] = o1[1] = o1[2] = o1[3] = 0.f; }
    if (w0 == 0)      { o0[0] = 0.f; o1[0] = 0.f; }
    if (w0 == WW - 4) { o0[3] = 0.f; o1[3] = 0.f; }

    *reinterpret_cast<float4*>(out + bc) = make_float4(o0[0], o0[1], o0[2], o0[3]);
    *reinterpret_cast<float4*>(out + bd) = make_float4(o1[0], o1[1], o1[2], o1[3]);
}

extern "C" void kernel_launch(void* const* d_in, const int* in_sizes, int n_in,
                              void* d_out, int out_size)
{
    const float* img   = (const float*)d_in[0];
    const float* theta = (const float*)d_in[1];
    float*       out   = (float*)d_out;

    const int n_threads = (HH / 2) * (WW / 4);   // 2,097,152
    const int block     = 256;
    const int grid      = n_threads / block;     // 8192
    nms_kernel<<<grid, block>>>(img, theta, out);
}

// round 6
// speedup vs baseline: 1.0115x; 1.0115x over previous
#include <cuda_runtime.h>

#define HH 4096
#define WW 4096
#define NPIX (HH * WW)

// Block = 2D tile: 64 quads (256 px) wide x 4 rows. Vertical neighbor re-reads
// hit the same SM's L1 instead of going back to L2 three times.

__global__ void __launch_bounds__(256, 7) nms_kernel(
    const float* __restrict__ img,
    const float* __restrict__ theta,
    float* __restrict__ out)
{
    unsigned tid = threadIdx.x;
    unsigned bx  = blockIdx.x & 15u;    // 16 tiles across (64 quads each)
    unsigned by  = blockIdx.x >> 4;     // 1024 tiles down (4 rows each)
    unsigned tx  = tid & 63u;           // quad within row strip
    unsigned ty  = tid >> 6;            // row within tile (0..3)

    unsigned h    = (by << 2) + ty;
    unsigned w0   = ((bx << 6) + tx) << 2;
    unsigned base = (h << 12) + w0;

    if (h == 0 || h == HH - 1) {
        __stcs(reinterpret_cast<float4*>(out + base), make_float4(0.f, 0.f, 0.f, 0.f));
        return;
    }

    const float* pc = img + base;   // single base; img loads at immediate offsets

    // ---- 10 independent loads, front-batched (MLP=10) ----
    const float4 t4 = __ldcs(reinterpret_cast<const float4*>(theta + base)); // read-once
    const float4 c4 = __ldg(reinterpret_cast<const float4*>(pc));
    const float4 u4 = __ldg(reinterpret_cast<const float4*>(pc - WW));
    const float4 d4 = __ldg(reinterpret_cast<const float4*>(pc + WW));

    // corner clamps only bind for border-zeroed outputs; values never used.
    int uli = (int)base - WW - 1; if (uli < 0) uli = 0;
    int dri = (int)base + WW + 4; if (dri >= NPIX) dri = NPIX - 1;

    const float lft = __ldg(pc - 1);
    const float rgt = __ldg(pc + 4);
    const float ul  = __ldg(img + uli);
    const float ur  = __ldg(pc - WW + 4);
    const float dl  = __ldg(pc + WW - 1);
    const float dr  = __ldg(img + dri);

    // column j = image column (w0 - 1 + j)
    float row[6] = { lft, c4.x, c4.y, c4.z, c4.w, rgt };
    float uu [6] = { ul,  u4.x, u4.y, u4.z, u4.w, ur  };
    float dn [6] = { dl,  d4.x, d4.y, d4.z, d4.w, dr  };
    float th [4] = { t4.x, t4.y, t4.z, t4.w };
    float o[4];

    const float RCP45 = 1.0f / 45.0f;   // RN(1/45)

    #pragma unroll
    for (int i = 0; i < 4; i++) {
        // deg = theta * f32(180/pi); single +180 if negative (matches reference)
        float deg = __fmul_rn(th[i], 57.29577951308232f);
        if (deg < 0.f) deg = __fadd_rn(deg, 180.f);

        // correctly-rounded deg/45 (Markstein mul+2fma, bit-exact vs RN divide)
        float q0 = __fmul_rn(deg, RCP45);
        float rr = __fmaf_rn(-45.f, q0, deg);
        float qf = __fmaf_rn(rr, RCP45, q0);
        int   k  = __float2int_rn(qf);      // F2I.RNI = round-half-even = jnp.round

        // k: 0 or 4 -> 0/180 deg; 1 -> 45; 2 -> 90; anything else -> 135
        float a, b;
        if (k == 0 || k == 4) { a = row[i + 2]; b = row[i];     }
        else if (k == 1)      { a = dn [i + 2]; b = uu[i];      }
        else if (k == 2)      { a = dn [i + 1]; b = uu[i + 1];  }
        else                  { a = dn [i];     b = uu[i + 2];  }

        float cc = row[i + 1];
        o[i] = (cc >= fmaxf(a, b)) ? cc : 0.f;
    }

    // left / right image borders
    if (w0 == 0)       o[0] = 0.f;
    if (w0 == WW - 4)  o[3] = 0.f;

    __stcs(reinterpret_cast<float4*>(out + base),
           make_float4(o[0], o[1], o[2], o[3]));     // never re-read: stream it
}

extern "C" void kernel_launch(void* const* d_in, const int* in_sizes, int n_in,
                              void* d_out, int out_size)
{
    const float* img   = (const float*)d_in[0];
    const float* theta = (const float*)d_in[1];
    float*       out   = (float*)d_out;

    const int grid = 16 * 1024;   // 16 tiles-x * 1024 tiles-y
    nms_kernel<<<grid, 256>>>(img, theta, out);
}